// round 13
// baseline (speedup 1.0000x reference)
#include <cuda_runtime.h>
#include <cuda_fp16.h>
#include <math.h>
#include <stdint.h>

#define Bsz 2
#define Lsz 1024
#define Hsz 2048
#define Msz (Bsz*Lsz)          // 2048 rows
#define NST 16
#define CHUNK 128
#define NCHUNK (Lsz/CHUNK)     // 8
#define DBC_SPLITS 8

// tc gemm tile (fp16 path) — R11 proven config
#define TM 128
#define TN 256
#define KC 64
#define DST 4
#define RS 72                               // padded row stride in halves
#define OFFB_H (128*RS)                     // B offset in halves
#define STG_H ((128+256)*RS)                // halves per stage (27648)
#define SMEM_TOT (DST*STG_H*2)              // 221184 bytes

// ---------------- scratch ----------------
__device__ __half d_h16[(size_t)Msz*Hsz];       // rmsnorm out (fp16)
__device__ __half d_xcp16[(size_t)Msz*Hsz];     // in_proj xc half (fp16)
__device__ float  d_z[(size_t)Msz*Hsz];         // in_proj z half (fp32)
__device__ float  d_xc[(size_t)Msz*Hsz];        // conv+silu out (fp32)
__device__ float  d_dbc[(size_t)Msz*96];
__device__ float  d_dbcp[(size_t)DBC_SPLITS*Msz*96];
__device__ float  d_delta[(size_t)Msz*Hsz];
__device__ __half d_g16[(size_t)Msz*Hsz];       // y*silu(z) (fp16)
__device__ float  d_Aexp[Hsz*NST];
__device__ float  d_P[(size_t)Bsz*NCHUNK*Hsz*NST];
__device__ float  d_S[(size_t)Bsz*NCHUNK*Hsz*NST];
__device__ float  d_I[(size_t)Bsz*NCHUNK*Hsz*NST];
__device__ __half d_ipw16[(size_t)2*Hsz*Hsz];   // in_proj_w fp16
__device__ __half d_opw16[(size_t)Hsz*Hsz];     // out_proj_w fp16
__device__ __half d_cwT16[(size_t)Hsz*4*Hsz];   // conv_w transposed [n][k=8192] fp16

// ---------------- helpers ----------------
__device__ __forceinline__ void mma16(float* c, const unsigned* a, const unsigned* b){
    asm volatile("mma.sync.aligned.m16n8k16.row.col.f32.f16.f16.f32 "
      "{%0,%1,%2,%3}, {%4,%5,%6,%7}, {%8,%9}, {%0,%1,%2,%3};"
      : "+f"(c[0]), "+f"(c[1]), "+f"(c[2]), "+f"(c[3])
      : "r"(a[0]), "r"(a[1]), "r"(a[2]), "r"(a[3]), "r"(b[0]), "r"(b[1]));
}
__device__ __forceinline__ void ldsm4(unsigned* r, uint32_t a){
    asm volatile("ldmatrix.sync.aligned.m8n8.x4.shared.b16 {%0,%1,%2,%3}, [%4];"
        : "=r"(r[0]), "=r"(r[1]), "=r"(r[2]), "=r"(r[3]) : "r"(a));
}
__device__ __forceinline__ uint32_t smem_u32(const void* p){
    uint32_t a; asm("{ .reg .u64 t; cvta.to.shared.u64 t, %1; cvt.u32.u64 %0, t; }" : "=r"(a) : "l"(p));
    return a;
}
__device__ __forceinline__ void cpa16(uint32_t dst, const __half* src, int srcsize){
    asm volatile("cp.async.cg.shared.global [%0], [%1], 16, %2;"
        :: "r"(dst), "l"(src), "r"(srcsize) : "memory");
}
__device__ __forceinline__ void cp_commit(){ asm volatile("cp.async.commit_group;" ::: "memory"); }
__device__ __forceinline__ void cp_wait2(){ asm volatile("cp.async.wait_group 2;" ::: "memory"); }

// ---------------- side prep (runs inside in_proj grid, z=1 CTAs) ----------------
// 256 blocks x 512 thr: convT (64 tiles each) + opw half (4096 uint4 each) + aexp (128 each)
__device__ void side_prep(int bid, int t, char* smemraw,
                          const float* __restrict__ opw,
                          const float* __restrict__ alog,
                          const float* __restrict__ cw){
    if (t < 128) {
        int i = bid*128 + t;                 // 256*128 = 32768 = Hsz*NST
        d_Aexp[i] = -expf(alog[i]);
    }
    {
        const size_t base = (size_t)bid*4096;    // 256*4096 = 1048576 = Hsz*Hsz/4
        for (int j = t; j < 4096; j += 512) {
            size_t i = base + j;
            float4 v = *(const float4*)(opw + i*4);
            __half2 h01 = __floats2half2_rn(v.x, v.y);
            __half2 h23 = __floats2half2_rn(v.z, v.w);
            *(uint2*)(d_opw16 + i*4) = make_uint2(*(unsigned*)&h01, *(unsigned*)&h23);
        }
    }
    float (*tl)[33] = (float(*)[33])smemraw;
    const int tx = t & 31, ty = t >> 5;          // ty 0..15
    for (int j = 0; j < 64; j++) {
        const int tid2 = bid*64 + j;             // 16384 tiles
        const int k0 = (tid2 & 255)*32, n0 = (tid2 >> 8)*32;
        __syncthreads();
        #pragma unroll
        for (int d = 0; d < 2; d++)
            tl[ty + d*16][tx] = cw[(size_t)(k0+ty+d*16)*Hsz + n0 + tx];
        __syncthreads();
        #pragma unroll
        for (int d = 0; d < 2; d++)
            d_cwT16[(size_t)(n0+ty+d*16)*(4*Hsz) + k0 + tx] = __float2half_rn(tl[tx][ty+d*16]);
    }
}

// ---------------- rmsnorm + ipw-half fused ----------------
#define NB_IPW 8192
__global__ void rmsprep(const float* __restrict__ x, const float* __restrict__ w,
                        const float* __restrict__ ipw){
    const int bid = blockIdx.x;
    if (bid < NB_IPW) {
        int i = bid*256 + threadIdx.x;           // 8192*256 = 2*Hsz*Hsz/4
        float4 v = *(const float4*)(ipw + (size_t)i*4);
        __half2 h01 = __floats2half2_rn(v.x, v.y);
        __half2 h23 = __floats2half2_rn(v.z, v.w);
        *(uint2*)(d_ipw16 + (size_t)i*4) = make_uint2(*(unsigned*)&h01, *(unsigned*)&h23);
        return;
    }
    const int m = bid - NB_IPW;
    const float* xr = x + (size_t)m*Hsz;
    float ss = 0.f;
    for (int i = threadIdx.x*4; i < Hsz; i += 1024) {
        float4 v = *(const float4*)(xr + i);
        ss += v.x*v.x + v.y*v.y + v.z*v.z + v.w*v.w;
    }
    __shared__ float red[8];
    #pragma unroll
    for (int o = 16; o; o >>= 1) ss += __shfl_xor_sync(0xffffffffu, ss, o);
    if ((threadIdx.x & 31) == 0) red[threadIdx.x >> 5] = ss;
    __syncthreads();
    if (threadIdx.x == 0) {
        float v = 0.f;
        #pragma unroll
        for (int j = 0; j < 8; j++) v += red[j];
        red[0] = rsqrtf(v * (1.0f/Hsz) + 1e-5f);
    }
    __syncthreads();
    const float sc = red[0];
    for (int i = threadIdx.x*4; i < Hsz; i += 1024) {
        float4 v = *(const float4*)(xr + i);
        float4 wv = *(const float4*)(w + i);
        __half2 h01 = __floats2half2_rn(v.x*sc*wv.x, v.y*sc*wv.y);
        __half2 h23 = __floats2half2_rn(v.z*sc*wv.z, v.w*sc*wv.w);
        *(uint2*)(d_h16 + (size_t)m*Hsz + i) = make_uint2(*(unsigned*)&h01, *(unsigned*)&h23);
    }
}

// ====== fp16 tensor GEMM (R11 config): 512 thr, 128x256 tile, DST=4, rotation ======
// EPI 0: in_proj split (n<H -> fp16 xcp, else -> fp32 z); z=1 CTAs run side_prep.
// EPI 1: conv bias+silu -> fp32 C      (CONVA: virtual causal-shifted A)
// EPI 2: resid add -> fp32 C
template<int EPI, bool CONVA>
__global__ void __launch_bounds__(512, 1)
gemm_tc(const __half* __restrict__ A, const __half* __restrict__ W,
        float* __restrict__ C, float* __restrict__ C2,
        const float* __restrict__ aux, int K, int lda, int ldc,
        const float* __restrict__ p_opw, const float* __restrict__ p_alog,
        const float* __restrict__ p_cw)
{
    extern __shared__ __align__(16) __half sm[];
    if (EPI == 0 && blockIdx.z == 1) {
        side_prep(blockIdx.y * 16 + blockIdx.x, threadIdx.x, (char*)sm, p_opw, p_alog, p_cw);
        return;
    }
    const uint32_t smb = smem_u32(sm);
    const int t = threadIdx.x;
    const int lane = t & 31, w = t >> 5;
    const int gid = lane >> 2, tig = lane & 3;
    const int wm = (w & 3) * 32, wn = (w >> 2) * 64;
    const int wrot = w & 3;
    const int n0 = blockIdx.x * TN, m0 = blockIdx.y * TM;
    const int nc = K / KC;

    uint32_t dstA[2], dstB[4];
    int rowA[2], kcA[2], rowB[4], kcB[4];
    #pragma unroll
    for (int i = 0; i < 2; i++) {
        int slot = t + 512*i;
        rowA[i] = slot >> 3; kcA[i] = (slot & 7) * 8;
        dstA[i] = smb + (uint32_t)(rowA[i]*RS + kcA[i])*2;
    }
    #pragma unroll
    for (int i = 0; i < 4; i++) {
        int slot = t + 512*i;
        rowB[i] = slot >> 3; kcB[i] = (slot & 7) * 8;
        dstB[i] = smb + (uint32_t)(OFFB_H + rowB[i]*RS + kcB[i])*2;
    }

    auto issue = [&](int c){
        if (c < nc) {
            const uint32_t so = (uint32_t)(c & (DST-1)) * (STG_H*2);
            const int kb = c * KC;
            if (!CONVA) {
                #pragma unroll
                for (int i = 0; i < 2; i++)
                    cpa16(dstA[i] + so, A + (size_t)(m0 + rowA[i])*lda + kb + kcA[i], 16);
            } else {
                const int tap = kb >> 11, kin = kb & (Hsz-1);
                #pragma unroll
                for (int i = 0; i < 2; i++) {
                    const int m = m0 + rowA[i];
                    int ls = (m & 1023) + tap - 3;
                    const int sz = (ls >= 0) ? 16 : 0;
                    if (ls < 0) ls = 0;
                    cpa16(dstA[i] + so, A + (size_t)((m & ~1023) + ls)*lda + kin + kcA[i], sz);
                }
            }
            #pragma unroll
            for (int i = 0; i < 4; i++)
                cpa16(dstB[i] + so, W + (size_t)(n0 + rowB[i])*K + kb + kcB[i], 16);
        }
        cp_commit();
    };

    uint32_t a_ad[2], b_ad[4];
    {
        const int arow = (lane & 15), acol = (lane >> 4) * 8;
        #pragma unroll
        for (int mi = 0; mi < 2; mi++)
            a_ad[mi] = smb + (uint32_t)(((wm + mi*16 + arow)*RS + acol))*2;
        const int brow = ((lane & 16) >> 1) + (lane & 7);
        const int bcol = (lane & 8);
        #pragma unroll
        for (int nq = 0; nq < 4; nq++)
            b_ad[nq] = smb + (uint32_t)((OFFB_H + (wn + nq*16 + brow)*RS + bcol))*2;
    }

    float acc[2][8][4];
    #pragma unroll
    for (int mi = 0; mi < 2; mi++)
        #pragma unroll
        for (int ni = 0; ni < 8; ni++)
            #pragma unroll
            for (int q = 0; q < 4; q++) acc[mi][ni][q] = 0.f;

    issue(0); issue(1); issue(2);
    for (int c = 0; c < nc; c++) {
        cp_wait2();
        __syncthreads();
        const uint32_t so = (uint32_t)(c & (DST-1)) * (STG_H*2);
        #pragma unroll
        for (int i = 0; i < 4; i++) {
            const int ks = (i + wrot) & 3;
            unsigned af[2][4], bf[4][4];
            ldsm4(af[0], a_ad[0] + so + ks*32);
            ldsm4(af[1], a_ad[1] + so + ks*32);
            #pragma unroll
            for (int nq = 0; nq < 4; nq++) ldsm4(bf[nq], b_ad[nq] + so + ks*32);
            #pragma unroll
            for (int mi = 0; mi < 2; mi++)
                #pragma unroll
                for (int ni = 0; ni < 8; ni++)
                    mma16(acc[mi][ni], af[mi], &bf[ni>>1][(ni&1)*2]);
        }
        issue(c + DST - 1);
    }

    #pragma unroll
    for (int mi = 0; mi < 2; mi++) {
        #pragma unroll
        for (int rr = 0; rr < 2; rr++) {
            const int m = m0 + wm + mi*16 + rr*8 + gid;
            #pragma unroll
            for (int ni = 0; ni < 8; ni++) {
                const int n = n0 + wn + ni*8 + tig*2;
                float v0 = acc[mi][ni][rr*2+0];
                float v1 = acc[mi][ni][rr*2+1];
                if (EPI == 0) {
                    if (n < Hsz) {
                        __half2 hp = __floats2half2_rn(v0, v1);
                        *(unsigned*)&d_xcp16[(size_t)m*Hsz + n] = *(unsigned*)&hp;
                    } else {
                        *(float2*)&C2[(size_t)m*ldc + n - Hsz] = make_float2(v0, v1);
                    }
                } else if (EPI == 1) {
                    v0 += aux[n];   v1 += aux[n+1];
                    v0 = v0 / (1.f + __expf(-v0));
                    v1 = v1 / (1.f + __expf(-v1));
                    *(float2*)&C[(size_t)m*ldc + n] = make_float2(v0, v1);
                } else {
                    v0 += aux[(size_t)m*ldc + n];
                    v1 += aux[(size_t)m*ldc + n + 1];
                    *(float2*)&C[(size_t)m*ldc + n] = make_float2(v0, v1);
                }
            }
        }
    }
}

// ---------------- fp32 SIMT GEMM (exact; small ops) ----------------
template<int EPI>
__global__ void __launch_bounds__(256)
gemm_wt(const float* __restrict__ A, const float* __restrict__ W,
        float* __restrict__ C, int M, int N, int K,
        int lda, int ldb, int ldc,
        const float* __restrict__ bias)
{
    __shared__ float As[8][128];
    __shared__ float Bs[8][128];
    const int t  = threadIdx.x;
    const int n0 = blockIdx.x * 128;
    const int m0 = blockIdx.y * 128;
    const int kslice = K / gridDim.z;
    const int kbeg = blockIdx.z * kslice;
    const int KT = kslice >> 3;

    const int ar = t >> 1;
    const int ak = (t & 1) * 4;
    const float* Ap = A + (size_t)(m0 + ar)*lda + kbeg + ak;
    const bool wok = (n0 + ar) < N;
    const float* Wp = W + (size_t)(n0 + ar)*ldb + kbeg + ak;

    float* Cb = C;
    if (EPI == 4) Cb = C + (size_t)blockIdx.z * M * ldc;

    const int tx = t & 15, ty = t >> 4;
    float acc[8][8];
    #pragma unroll
    for (int i = 0; i < 8; i++)
        #pragma unroll
        for (int j = 0; j < 8; j++) acc[i][j] = 0.f;

    float4 pa = *(const float4*)Ap;
    float4 pb = wok ? *(const float4*)Wp : make_float4(0.f,0.f,0.f,0.f);

    for (int kt = 0; kt < KT; ++kt) {
        As[ak+0][ar]=pa.x; As[ak+1][ar]=pa.y; As[ak+2][ar]=pa.z; As[ak+3][ar]=pa.w;
        Bs[ak+0][ar]=pb.x; Bs[ak+1][ar]=pb.y; Bs[ak+2][ar]=pb.z; Bs[ak+3][ar]=pb.w;
        __syncthreads();
        if (kt + 1 < KT) {
            pa = *(const float4*)(Ap + (size_t)(kt+1)*8);
            pb = wok ? *(const float4*)(Wp + (size_t)(kt+1)*8) : make_float4(0.f,0.f,0.f,0.f);
        }
        #pragma unroll
        for (int kk = 0; kk < 8; kk++) {
            float a[8], b[8];
            *(float4*)&a[0] = *(const float4*)&As[kk][ty*8];
            *(float4*)&a[4] = *(const float4*)&As[kk][ty*8+4];
            *(float4*)&b[0] = *(const float4*)&Bs[kk][tx*8];
            *(float4*)&b[4] = *(const float4*)&Bs[kk][tx*8+4];
            #pragma unroll
            for (int i = 0; i < 8; i++)
                #pragma unroll
                for (int j = 0; j < 8; j++)
                    acc[i][j] = fmaf(a[i], b[j], acc[i][j]);
        }
        __syncthreads();
    }

    #pragma unroll
    for (int i = 0; i < 8; i++) {
        const int m = m0 + ty*8 + i;
        #pragma unroll
        for (int j = 0; j < 8; j++) {
            const int n = n0 + tx*8 + j;
            if (n < N) {
                float v = acc[i][j];
                if (EPI == 2) { v += bias[n]; v = (v > 20.f) ? v : log1pf(__expf(v)); }
                Cb[(size_t)m*ldc + n] = v;
            }
        }
    }
}

__global__ void reduce_dbc() {
    int i = blockIdx.x*256 + threadIdx.x;
    if (i < Msz*96) {
        float s = 0.f;
        #pragma unroll
        for (int z = 0; z < DBC_SPLITS; z++) s += d_dbcp[(size_t)z*Msz*96 + i];
        d_dbc[i] = s;
    }
}

// ---------------- chunked selective scan (fast path: a[n] == -(n+1)) ----------------
__global__ void __launch_bounds__(128) scan_pass1() {
    __shared__ float sB[CHUNK][NST];
    const int bid = blockIdx.x;
    const int ht = bid & 15;
    const int c  = (bid >> 4) & 7;
    const int b  = bid >> 7;
    const int h  = ht*128 + threadIdx.x;
    const int mbase = b*Lsz + c*CHUNK;

    for (int j = threadIdx.x; j < CHUNK*NST; j += 128) {
        int l = j >> 4, n = j & 15;
        sB[l][n] = d_dbc[(size_t)(mbase+l)*96 + 64 + n];
    }
    __syncthreads();

    float a[NST], p[NST], s[NST];
    bool fastok = true;
    #pragma unroll
    for (int n = 0; n < NST; n++) {
        a[n] = d_Aexp[h*NST + n];
        p[n] = 1.f; s[n] = 0.f;
        fastok = fastok && (fabsf(a[n] + (float)(n+1)) <= 2e-6f*(float)(n+1));
    }

    if (fastok) {
        float Dsum = 0.f;
        for (int l = 0; l < CHUNK; l++) {
            const float dl = d_delta[(size_t)(mbase+l)*Hsz + h];
            const float xv = d_xc[(size_t)(mbase+l)*Hsz + h];
            const float q = __expf(-dl);
            const float du = dl * xv;
            Dsum += dl;
            float rq = q;
            #pragma unroll
            for (int n = 0; n < NST; n++) {
                s[n] = fmaf(rq, s[n], du * sB[l][n]);
                rq *= q;
            }
        }
        const float Q = __expf(-Dsum);
        float pq = Q;
        #pragma unroll
        for (int n = 0; n < NST; n++) { p[n] = pq; pq *= Q; }
    } else {
        for (int l = 0; l < CHUNK; l++) {
            const float dl = d_delta[(size_t)(mbase+l)*Hsz + h];
            const float xv = d_xc[(size_t)(mbase+l)*Hsz + h];
            const float du = dl * xv;
            #pragma unroll
            for (int n = 0; n < NST; n++) {
                float r = __expf(dl * a[n]);
                p[n] *= r;
                s[n] = fmaf(r, s[n], du * sB[l][n]);
            }
        }
    }
    size_t base = ((size_t)(b*NCHUNK + c)*Hsz + h)*NST;
    #pragma unroll
    for (int n = 0; n < NST; n++) { d_P[base+n] = p[n]; d_S[base+n] = s[n]; }
}

__global__ void scan_pass2() {
    int idx = blockIdx.x*256 + threadIdx.x;
    if (idx >= Bsz*Hsz*NST) return;
    int b  = idx / (Hsz*NST);
    int hn = idx % (Hsz*NST);
    float st = 0.f;
    for (int c = 0; c < NCHUNK; c++) {
        size_t o = (size_t)(b*NCHUNK + c)*Hsz*NST + hn;
        d_I[o] = st;
        st = d_P[o]*st + d_S[o];
    }
}

__global__ void __launch_bounds__(128) scan_pass3(const float* __restrict__ Din) {
    __shared__ float sBC[CHUNK][2*NST];
    const int bid = blockIdx.x;
    const int ht = bid & 15;
    const int c  = (bid >> 4) & 7;
    const int b  = bid >> 7;
    const int h  = ht*128 + threadIdx.x;
    const int mbase = b*Lsz + c*CHUNK;

    for (int j = threadIdx.x; j < CHUNK*2*NST; j += 128) {
        int l = j >> 5, cc = j & 31;
        sBC[l][cc] = d_dbc[(size_t)(mbase+l)*96 + 64 + cc];
    }
    __syncthreads();

    float a[NST], s[NST];
    size_t base = ((size_t)(b*NCHUNK + c)*Hsz + h)*NST;
    bool fastok = true;
    #pragma unroll
    for (int n = 0; n < NST; n++) {
        a[n] = d_Aexp[h*NST + n];
        s[n] = d_I[base+n];
        fastok = fastok && (fabsf(a[n] + (float)(n+1)) <= 2e-6f*(float)(n+1));
    }
    const float Dh = Din[h];

    if (fastok) {
        for (int l = 0; l < CHUNK; l++) {
            const float dl = d_delta[(size_t)(mbase+l)*Hsz + h];
            const float xv = d_xc[(size_t)(mbase+l)*Hsz + h];
            const float q = __expf(-dl);
            const float du = dl * xv;
            float y = 0.f, rq = q;
            #pragma unroll
            for (int n = 0; n < NST; n++) {
                s[n] = fmaf(rq, s[n], du * sBC[l][n]);
                y = fmaf(s[n], sBC[l][NST+n], y);
                rq *= q;
            }
            y = fmaf(Dh, xv, y);
            const int m = mbase + l;
            float z = d_z[(size_t)m*Hsz + h];
            float sz = z / (1.f + __expf(-z));
            d_g16[(size_t)m*Hsz + h] = __float2half_rn(y * sz);
        }
    } else {
        for (int l = 0; l < CHUNK; l++) {
            const float dl = d_delta[(size_t)(mbase+l)*Hsz + h];
            const float xv = d_xc[(size_t)(mbase+l)*Hsz + h];
            const float du = dl * xv;
            float y = 0.f;
            #pragma unroll
            for (int n = 0; n < NST; n++) {
                float r = __expf(dl * a[n]);
                s[n] = fmaf(r, s[n], du * sBC[l][n]);
                y = fmaf(s[n], sBC[l][NST+n], y);
            }
            y = fmaf(Dh, xv, y);
            const int m = mbase + l;
            float z = d_z[(size_t)m*Hsz + h];
            float sz = z / (1.f + __expf(-z));
            d_g16[(size_t)m*Hsz + h] = __float2half_rn(y * sz);
        }
    }
}

// ---------------- launch ----------------
extern "C" void kernel_launch(void* const* d_in, const int* in_sizes, int n_in,
                              void* d_out, int out_size) {
    const float* x          = (const float*)d_in[0];
    const float* norm_w     = (const float*)d_in[1];
    const float* in_proj_w  = (const float*)d_in[2];
    const float* conv_w     = (const float*)d_in[3];
    const float* conv_b     = (const float*)d_in[4];
    const float* x_proj_w   = (const float*)d_in[5];
    const float* dt_proj_w  = (const float*)d_in[6];
    const float* dt_proj_b  = (const float*)d_in[7];
    const float* A_log      = (const float*)d_in[8];
    const float* Dv         = (const float*)d_in[9];
    const float* out_proj_w = (const float*)d_in[10];
    float* out = (float*)d_out;

    static int attr_done = 0;
    if (!attr_done) {
        cudaFuncSetAttribute(gemm_tc<0,false>, cudaFuncAttributeMaxDynamicSharedMemorySize, SMEM_TOT);
        cudaFuncSetAttribute(gemm_tc<1,true >, cudaFuncAttributeMaxDynamicSharedMemorySize, SMEM_TOT);
        cudaFuncSetAttribute(gemm_tc<2,false>, cudaFuncAttributeMaxDynamicSharedMemorySize, SMEM_TOT);
        attr_done = 1;
    }

    __half *p_h16, *p_xcp16, *p_g16, *p_ipw16, *p_opw16, *p_cwT16;
    float *p_z, *p_xc, *p_dbc, *p_dbcp, *p_delta;
    cudaGetSymbolAddress((void**)&p_h16, d_h16);
    cudaGetSymbolAddress((void**)&p_xcp16, d_xcp16);
    cudaGetSymbolAddress((void**)&p_g16, d_g16);
    cudaGetSymbolAddress((void**)&p_ipw16, d_ipw16);
    cudaGetSymbolAddress((void**)&p_opw16, d_opw16);
    cudaGetSymbolAddress((void**)&p_cwT16, d_cwT16);
    cudaGetSymbolAddress((void**)&p_z, d_z);
    cudaGetSymbolAddress((void**)&p_xc, d_xc);
    cudaGetSymbolAddress((void**)&p_dbc, d_dbc);
    cudaGetSymbolAddress((void**)&p_dbcp, d_dbcp);
    cudaGetSymbolAddress((void**)&p_delta, d_delta);

    // launch 1: rmsnorm + ipw-half (fused grids)
    rmsprep<<<NB_IPW + Msz, 256>>>(x, norm_w, in_proj_w);
    // launch 2: in_proj (z=0: GEMM M=2048 N=4096 K=2048; z=1: side prep filling tail wave)
    gemm_tc<0,false><<<dim3(2*Hsz/TN, Msz/TM, 2), 512, SMEM_TOT>>>(
        p_h16, p_ipw16, nullptr, p_z, nullptr, Hsz, Hsz, Hsz,
        out_proj_w, A_log, conv_w);
    // launch 3: conv  (K=8192 virtual over 4 taps)
    gemm_tc<1,true><<<dim3(Hsz/TN, Msz/TM, 1), 512, SMEM_TOT>>>(
        p_xcp16, p_cwT16, p_xc, nullptr, conv_b, 4*Hsz, Hsz, Hsz,
        nullptr, nullptr, nullptr);
    // dBC = xc @ x_proj_w.T  (exact fp32, split-K)
    gemm_wt<4><<<dim3(1,16,DBC_SPLITS), 256>>>(p_xc, x_proj_w, p_dbcp,
                                               Msz, 96, Hsz, Hsz, Hsz, 96, nullptr);
    reduce_dbc<<<(Msz*96 + 255)/256, 256>>>();
    // delta = softplus(dBC[:, :64] @ dt_proj_w.T + b)  (exact fp32)
    gemm_wt<2><<<dim3(16,16,1), 256>>>(p_dbc, dt_proj_w, p_delta,
                                       Msz, Hsz, 64, 96, 64, Hsz, dt_proj_b);
    // chunked selective scan -> g (fp16)
    scan_pass1<<<Bsz*NCHUNK*(Hsz/128), 128>>>();
    scan_pass2<<<(Bsz*Hsz*NST + 255)/256, 256>>>();
    scan_pass3<<<Bsz*NCHUNK*(Hsz/128), 128>>>(Dv);
    // out = x + g @ out_proj_w.T
    gemm_tc<2,false><<<dim3(Hsz/TN, Msz/TM, 1), 512, SMEM_TOT>>>(
        p_g16, p_opw16, out, nullptr, x, Hsz, Hsz, Hsz,
        nullptr, nullptr, nullptr);
}

// round 14
// speedup vs baseline: 1.0737x; 1.0737x over previous
#include <cuda_runtime.h>
#include <cuda_fp16.h>
#include <math.h>
#include <stdint.h>

#define Bsz 2
#define Lsz 1024
#define Hsz 2048
#define Msz (Bsz*Lsz)          // 2048 rows
#define NST 16
#define CHUNK 128
#define NCHUNK (Lsz/CHUNK)     // 8
#define DBC_SPLITS 16

// tc gemm tile (fp16 path) — R11 proven config
#define TM 128
#define TN 256
#define KC 64
#define DST 4
#define RS 72                               // padded row stride in halves
#define OFFB_H (128*RS)                     // B offset in halves
#define STG_H ((128+256)*RS)                // halves per stage (27648)
#define SMEM_TOT (DST*STG_H*2)              // 221184 bytes

// ---------------- scratch ----------------
__device__ __half d_h16[(size_t)Msz*Hsz];       // rmsnorm out (fp16)
__device__ __half d_xcp16[(size_t)Msz*Hsz];     // in_proj xc half (fp16)
__device__ float  d_z[(size_t)Msz*Hsz];         // in_proj z half (fp32)
__device__ float  d_xc[(size_t)Msz*Hsz];        // conv+silu out (fp32)
__device__ float  d_dbc[(size_t)Msz*96];
__device__ float  d_dbcp[(size_t)DBC_SPLITS*Msz*96];
__device__ float  d_delta[(size_t)Msz*Hsz];
__device__ __half d_g16[(size_t)Msz*Hsz];       // y*silu(z) (fp16)
__device__ float  d_Aexp[Hsz*NST];
__device__ float  d_P[(size_t)Bsz*NCHUNK*Hsz*NST];
__device__ float  d_S[(size_t)Bsz*NCHUNK*Hsz*NST];
__device__ float  d_I[(size_t)Bsz*NCHUNK*Hsz*NST];
__device__ __half d_ipw16[(size_t)2*Hsz*Hsz];   // in_proj_w fp16
__device__ __half d_opw16[(size_t)Hsz*Hsz];     // out_proj_w fp16
__device__ __half d_cwT16[(size_t)Hsz*4*Hsz];   // conv_w transposed [n][k=8192] fp16

// ---------------- helpers ----------------
__device__ __forceinline__ void mma16(float* c, const unsigned* a, const unsigned* b){
    asm volatile("mma.sync.aligned.m16n8k16.row.col.f32.f16.f16.f32 "
      "{%0,%1,%2,%3}, {%4,%5,%6,%7}, {%8,%9}, {%0,%1,%2,%3};"
      : "+f"(c[0]), "+f"(c[1]), "+f"(c[2]), "+f"(c[3])
      : "r"(a[0]), "r"(a[1]), "r"(a[2]), "r"(a[3]), "r"(b[0]), "r"(b[1]));
}
__device__ __forceinline__ void ldsm4(unsigned* r, uint32_t a){
    asm volatile("ldmatrix.sync.aligned.m8n8.x4.shared.b16 {%0,%1,%2,%3}, [%4];"
        : "=r"(r[0]), "=r"(r[1]), "=r"(r[2]), "=r"(r[3]) : "r"(a));
}
__device__ __forceinline__ uint32_t smem_u32(const void* p){
    uint32_t a; asm("{ .reg .u64 t; cvta.to.shared.u64 t, %1; cvt.u32.u64 %0, t; }" : "=r"(a) : "l"(p));
    return a;
}
__device__ __forceinline__ void cpa16(uint32_t dst, const __half* src, int srcsize){
    asm volatile("cp.async.cg.shared.global [%0], [%1], 16, %2;"
        :: "r"(dst), "l"(src), "r"(srcsize) : "memory");
}
__device__ __forceinline__ void cp_commit(){ asm volatile("cp.async.commit_group;" ::: "memory"); }
__device__ __forceinline__ void cp_wait2(){ asm volatile("cp.async.wait_group 2;" ::: "memory"); }

// ---------------- fused prep kernel ----------------
#define NB_IPW 8192
#define NB_OPW 4096
#define NB_AEXP 128
__global__ void prep_kernel(const float* __restrict__ ipw, const float* __restrict__ opw,
                            const float* __restrict__ alog, const float* __restrict__ cw){
    __shared__ float tl[32][33];
    const int bid = blockIdx.x;
    const int t = threadIdx.x;
    if (bid < NB_IPW) {
        int i = bid*256 + t;
        float4 v = *(const float4*)(ipw + (size_t)i*4);
        __half2 h01 = __floats2half2_rn(v.x, v.y);
        __half2 h23 = __floats2half2_rn(v.z, v.w);
        *(uint2*)(d_ipw16 + (size_t)i*4) = make_uint2(*(unsigned*)&h01, *(unsigned*)&h23);
    } else if (bid < NB_IPW + NB_OPW) {
        int i = (bid - NB_IPW)*256 + t;
        float4 v = *(const float4*)(opw + (size_t)i*4);
        __half2 h01 = __floats2half2_rn(v.x, v.y);
        __half2 h23 = __floats2half2_rn(v.z, v.w);
        *(uint2*)(d_opw16 + (size_t)i*4) = make_uint2(*(unsigned*)&h01, *(unsigned*)&h23);
    } else if (bid < NB_IPW + NB_OPW + NB_AEXP) {
        int i = (bid - NB_IPW - NB_OPW)*256 + t;
        if (i < Hsz*NST) d_Aexp[i] = -expf(alog[i]);
    } else {
        const int id = bid - (NB_IPW + NB_OPW + NB_AEXP);
        const int k0 = (id & 255)*32, n0 = (id >> 8)*32;
        const int tx = t & 31, ty = t >> 5;
        #pragma unroll
        for (int d = 0; d < 4; d++)
            tl[ty + d*8][tx] = cw[(size_t)(k0+ty+d*8)*Hsz + n0 + tx];
        __syncthreads();
        #pragma unroll
        for (int d = 0; d < 4; d++)
            d_cwT16[(size_t)(n0+ty+d*8)*(4*Hsz) + k0 + tx] = __float2half_rn(tl[tx][ty+d*8]);
    }
}

__global__ void rmsnorm_kernel(const float* __restrict__ x, const float* __restrict__ w) {
    const int m = blockIdx.x;
    const float* xr = x + (size_t)m*Hsz;
    float ss = 0.f;
    for (int i = threadIdx.x*4; i < Hsz; i += 1024) {
        float4 v = *(const float4*)(xr + i);
        ss += v.x*v.x + v.y*v.y + v.z*v.z + v.w*v.w;
    }
    __shared__ float red[8];
    #pragma unroll
    for (int o = 16; o; o >>= 1) ss += __shfl_xor_sync(0xffffffffu, ss, o);
    if ((threadIdx.x & 31) == 0) red[threadIdx.x >> 5] = ss;
    __syncthreads();
    if (threadIdx.x == 0) {
        float v = 0.f;
        #pragma unroll
        for (int j = 0; j < 8; j++) v += red[j];
        red[0] = rsqrtf(v * (1.0f/Hsz) + 1e-5f);
    }
    __syncthreads();
    const float sc = red[0];
    for (int i = threadIdx.x*4; i < Hsz; i += 1024) {
        float4 v = *(const float4*)(xr + i);
        float4 wv = *(const float4*)(w + i);
        __half2 h01 = __floats2half2_rn(v.x*sc*wv.x, v.y*sc*wv.y);
        __half2 h23 = __floats2half2_rn(v.z*sc*wv.z, v.w*sc*wv.w);
        *(uint2*)(d_h16 + (size_t)m*Hsz + i) = make_uint2(*(unsigned*)&h01, *(unsigned*)&h23);
    }
}

// ====== fp16 tensor GEMM (R11 config): 512 thr, 128x256 tile, DST=4, rotation ======
// EPI 0: in_proj split (n<H -> fp16 xcp, else -> fp32 z)
// EPI 1: conv bias+silu -> fp32 C      (CONVA: virtual causal-shifted A)
// EPI 2: resid add -> fp32 C
template<int EPI, bool CONVA>
__global__ void __launch_bounds__(512, 1)
gemm_tc(const __half* __restrict__ A, const __half* __restrict__ W,
        float* __restrict__ C, float* __restrict__ C2,
        const float* __restrict__ aux, int K, int lda, int ldc)
{
    extern __shared__ __align__(16) __half sm[];
    const uint32_t smb = smem_u32(sm);
    const int t = threadIdx.x;
    const int lane = t & 31, w = t >> 5;
    const int gid = lane >> 2, tig = lane & 3;
    const int wm = (w & 3) * 32, wn = (w >> 2) * 64;
    const int wrot = w & 3;
    const int n0 = blockIdx.x * TN, m0 = blockIdx.y * TM;
    const int nc = K / KC;

    uint32_t dstA[2], dstB[4];
    int rowA[2], kcA[2], rowB[4], kcB[4];
    #pragma unroll
    for (int i = 0; i < 2; i++) {
        int slot = t + 512*i;
        rowA[i] = slot >> 3; kcA[i] = (slot & 7) * 8;
        dstA[i] = smb + (uint32_t)(rowA[i]*RS + kcA[i])*2;
    }
    #pragma unroll
    for (int i = 0; i < 4; i++) {
        int slot = t + 512*i;
        rowB[i] = slot >> 3; kcB[i] = (slot & 7) * 8;
        dstB[i] = smb + (uint32_t)(OFFB_H + rowB[i]*RS + kcB[i])*2;
    }

    auto issue = [&](int c){
        if (c < nc) {
            const uint32_t so = (uint32_t)(c & (DST-1)) * (STG_H*2);
            const int kb = c * KC;
            if (!CONVA) {
                #pragma unroll
                for (int i = 0; i < 2; i++)
                    cpa16(dstA[i] + so, A + (size_t)(m0 + rowA[i])*lda + kb + kcA[i], 16);
            } else {
                const int tap = kb >> 11, kin = kb & (Hsz-1);
                #pragma unroll
                for (int i = 0; i < 2; i++) {
                    const int m = m0 + rowA[i];
                    int ls = (m & 1023) + tap - 3;
                    const int sz = (ls >= 0) ? 16 : 0;
                    if (ls < 0) ls = 0;
                    cpa16(dstA[i] + so, A + (size_t)((m & ~1023) + ls)*lda + kin + kcA[i], sz);
                }
            }
            #pragma unroll
            for (int i = 0; i < 4; i++)
                cpa16(dstB[i] + so, W + (size_t)(n0 + rowB[i])*K + kb + kcB[i], 16);
        }
        cp_commit();
    };

    uint32_t a_ad[2], b_ad[4];
    {
        const int arow = (lane & 15), acol = (lane >> 4) * 8;
        #pragma unroll
        for (int mi = 0; mi < 2; mi++)
            a_ad[mi] = smb + (uint32_t)(((wm + mi*16 + arow)*RS + acol))*2;
        const int brow = ((lane & 16) >> 1) + (lane & 7);
        const int bcol = (lane & 8);
        #pragma unroll
        for (int nq = 0; nq < 4; nq++)
            b_ad[nq] = smb + (uint32_t)((OFFB_H + (wn + nq*16 + brow)*RS + bcol))*2;
    }

    float acc[2][8][4];
    #pragma unroll
    for (int mi = 0; mi < 2; mi++)
        #pragma unroll
        for (int ni = 0; ni < 8; ni++)
            #pragma unroll
            for (int q = 0; q < 4; q++) acc[mi][ni][q] = 0.f;

    issue(0); issue(1); issue(2);
    for (int c = 0; c < nc; c++) {
        cp_wait2();
        __syncthreads();
        const uint32_t so = (uint32_t)(c & (DST-1)) * (STG_H*2);
        #pragma unroll
        for (int i = 0; i < 4; i++) {
            const int ks = (i + wrot) & 3;
            unsigned af[2][4], bf[4][4];
            ldsm4(af[0], a_ad[0] + so + ks*32);
            ldsm4(af[1], a_ad[1] + so + ks*32);
            #pragma unroll
            for (int nq = 0; nq < 4; nq++) ldsm4(bf[nq], b_ad[nq] + so + ks*32);
            #pragma unroll
            for (int mi = 0; mi < 2; mi++)
                #pragma unroll
                for (int ni = 0; ni < 8; ni++)
                    mma16(acc[mi][ni], af[mi], &bf[ni>>1][(ni&1)*2]);
        }
        issue(c + DST - 1);
    }

    #pragma unroll
    for (int mi = 0; mi < 2; mi++) {
        #pragma unroll
        for (int rr = 0; rr < 2; rr++) {
            const int m = m0 + wm + mi*16 + rr*8 + gid;
            #pragma unroll
            for (int ni = 0; ni < 8; ni++) {
                const int n = n0 + wn + ni*8 + tig*2;
                float v0 = acc[mi][ni][rr*2+0];
                float v1 = acc[mi][ni][rr*2+1];
                if (EPI == 0) {
                    if (n < Hsz) {
                        __half2 hp = __floats2half2_rn(v0, v1);
                        *(unsigned*)&d_xcp16[(size_t)m*Hsz + n] = *(unsigned*)&hp;
                    } else {
                        *(float2*)&C2[(size_t)m*ldc + n - Hsz] = make_float2(v0, v1);
                    }
                } else if (EPI == 1) {
                    v0 += aux[n];   v1 += aux[n+1];
                    v0 = v0 / (1.f + __expf(-v0));
                    v1 = v1 / (1.f + __expf(-v1));
                    *(float2*)&C[(size_t)m*ldc + n] = make_float2(v0, v1);
                } else {
                    v0 += aux[(size_t)m*ldc + n];
                    v1 += aux[(size_t)m*ldc + n + 1];
                    *(float2*)&C[(size_t)m*ldc + n] = make_float2(v0, v1);
                }
            }
        }
    }
}

// ---------------- fp32 SIMT GEMM (exact; small ops), 2 CTAs/SM ----------------
template<int EPI>
__global__ void __launch_bounds__(256, 2)
gemm_wt(const float* __restrict__ A, const float* __restrict__ W,
        float* __restrict__ C, int M, int N, int K,
        int lda, int ldb, int ldc,
        const float* __restrict__ bias)
{
    __shared__ float As[8][128];
    __shared__ float Bs[8][128];
    const int t  = threadIdx.x;
    const int n0 = blockIdx.x * 128;
    const int m0 = blockIdx.y * 128;
    const int kslice = K / gridDim.z;
    const int kbeg = blockIdx.z * kslice;
    const int KT = kslice >> 3;

    const int ar = t >> 1;
    const int ak = (t & 1) * 4;
    const float* Ap = A + (size_t)(m0 + ar)*lda + kbeg + ak;
    const bool wok = (n0 + ar) < N;
    const float* Wp = W + (size_t)(n0 + ar)*ldb + kbeg + ak;

    float* Cb = C;
    if (EPI == 4) Cb = C + (size_t)blockIdx.z * M * ldc;

    const int tx = t & 15, ty = t >> 4;
    float acc[8][8];
    #pragma unroll
    for (int i = 0; i < 8; i++)
        #pragma unroll
        for (int j = 0; j < 8; j++) acc[i][j] = 0.f;

    float4 pa = *(const float4*)Ap;
    float4 pb = wok ? *(const float4*)Wp : make_float4(0.f,0.f,0.f,0.f);

    for (int kt = 0; kt < KT; ++kt) {
        As[ak+0][ar]=pa.x; As[ak+1][ar]=pa.y; As[ak+2][ar]=pa.z; As[ak+3][ar]=pa.w;
        Bs[ak+0][ar]=pb.x; Bs[ak+1][ar]=pb.y; Bs[ak+2][ar]=pb.z; Bs[ak+3][ar]=pb.w;
        __syncthreads();
        if (kt + 1 < KT) {
            pa = *(const float4*)(Ap + (size_t)(kt+1)*8);
            pb = wok ? *(const float4*)(Wp + (size_t)(kt+1)*8) : make_float4(0.f,0.f,0.f,0.f);
        }
        #pragma unroll
        for (int kk = 0; kk < 8; kk++) {
            float a[8], b[8];
            *(float4*)&a[0] = *(const float4*)&As[kk][ty*8];
            *(float4*)&a[4] = *(const float4*)&As[kk][ty*8+4];
            *(float4*)&b[0] = *(const float4*)&Bs[kk][tx*8];
            *(float4*)&b[4] = *(const float4*)&Bs[kk][tx*8+4];
            #pragma unroll
            for (int i = 0; i < 8; i++)
                #pragma unroll
                for (int j = 0; j < 8; j++)
                    acc[i][j] = fmaf(a[i], b[j], acc[i][j]);
        }
        __syncthreads();
    }

    #pragma unroll
    for (int i = 0; i < 8; i++) {
        const int m = m0 + ty*8 + i;
        #pragma unroll
        for (int j = 0; j < 8; j++) {
            const int n = n0 + tx*8 + j;
            if (n < N) {
                float v = acc[i][j];
                if (EPI == 2) { v += bias[n]; v = (v > 20.f) ? v : log1pf(__expf(v)); }
                Cb[(size_t)m*ldc + n] = v;
            }
        }
    }
}

__global__ void reduce_dbc() {
    int i = blockIdx.x*256 + threadIdx.x;
    if (i < Msz*96) {
        float s = 0.f;
        #pragma unroll
        for (int z = 0; z < DBC_SPLITS; z++) s += d_dbcp[(size_t)z*Msz*96 + i];
        d_dbc[i] = s;
    }
}

// ---------------- chunked selective scan (fast path: a[n] == -(n+1)) ----------------
__global__ void __launch_bounds__(128) scan_pass1() {
    __shared__ float sB[CHUNK][NST];
    const int bid = blockIdx.x;
    const int ht = bid & 15;
    const int c  = (bid >> 4) & 7;
    const int b  = bid >> 7;
    const int h  = ht*128 + threadIdx.x;
    const int mbase = b*Lsz + c*CHUNK;

    for (int j = threadIdx.x; j < CHUNK*NST; j += 128) {
        int l = j >> 4, n = j & 15;
        sB[l][n] = d_dbc[(size_t)(mbase+l)*96 + 64 + n];
    }
    __syncthreads();

    float a[NST], p[NST], s[NST];
    bool fastok = true;
    #pragma unroll
    for (int n = 0; n < NST; n++) {
        a[n] = d_Aexp[h*NST + n];
        p[n] = 1.f; s[n] = 0.f;
        fastok = fastok && (fabsf(a[n] + (float)(n+1)) <= 2e-6f*(float)(n+1));
    }

    if (fastok) {
        float Dsum = 0.f;
        for (int l = 0; l < CHUNK; l++) {
            const float dl = d_delta[(size_t)(mbase+l)*Hsz + h];
            const float xv = d_xc[(size_t)(mbase+l)*Hsz + h];
            const float q = __expf(-dl);
            const float du = dl * xv;
            Dsum += dl;
            float rq = q;
            #pragma unroll
            for (int n = 0; n < NST; n++) {
                s[n] = fmaf(rq, s[n], du * sB[l][n]);
                rq *= q;
            }
        }
        const float Q = __expf(-Dsum);
        float pq = Q;
        #pragma unroll
        for (int n = 0; n < NST; n++) { p[n] = pq; pq *= Q; }
    } else {
        for (int l = 0; l < CHUNK; l++) {
            const float dl = d_delta[(size_t)(mbase+l)*Hsz + h];
            const float xv = d_xc[(size_t)(mbase+l)*Hsz + h];
            const float du = dl * xv;
            #pragma unroll
            for (int n = 0; n < NST; n++) {
                float r = __expf(dl * a[n]);
                p[n] *= r;
                s[n] = fmaf(r, s[n], du * sB[l][n]);
            }
        }
    }
    size_t base = ((size_t)(b*NCHUNK + c)*Hsz + h)*NST;
    #pragma unroll
    for (int n = 0; n < NST; n++) { d_P[base+n] = p[n]; d_S[base+n] = s[n]; }
}

__global__ void scan_pass2() {
    int idx = blockIdx.x*256 + threadIdx.x;
    if (idx >= Bsz*Hsz*NST) return;
    int b  = idx / (Hsz*NST);
    int hn = idx % (Hsz*NST);
    float st = 0.f;
    for (int c = 0; c < NCHUNK; c++) {
        size_t o = (size_t)(b*NCHUNK + c)*Hsz*NST + hn;
        d_I[o] = st;
        st = d_P[o]*st + d_S[o];
    }
}

__global__ void __launch_bounds__(128) scan_pass3(const float* __restrict__ Din) {
    __shared__ float sBC[CHUNK][2*NST];
    const int bid = blockIdx.x;
    const int ht = bid & 15;
    const int c  = (bid >> 4) & 7;
    const int b  = bid >> 7;
    const int h  = ht*128 + threadIdx.x;
    const int mbase = b*Lsz + c*CHUNK;

    for (int j = threadIdx.x; j < CHUNK*2*NST; j += 128) {
        int l = j >> 5, cc = j & 31;
        sBC[l][cc] = d_dbc[(size_t)(mbase+l)*96 + 64 + cc];
    }
    __syncthreads();

    float a[NST], s[NST];
    size_t base = ((size_t)(b*NCHUNK + c)*Hsz + h)*NST;
    bool fastok = true;
    #pragma unroll
    for (int n = 0; n < NST; n++) {
        a[n] = d_Aexp[h*NST + n];
        s[n] = d_I[base+n];
        fastok = fastok && (fabsf(a[n] + (float)(n+1)) <= 2e-6f*(float)(n+1));
    }
    const float Dh = Din[h];

    if (fastok) {
        for (int l = 0; l < CHUNK; l++) {
            const float dl = d_delta[(size_t)(mbase+l)*Hsz + h];
            const float xv = d_xc[(size_t)(mbase+l)*Hsz + h];
            const float q = __expf(-dl);
            const float du = dl * xv;
            float y = 0.f, rq = q;
            #pragma unroll
            for (int n = 0; n < NST; n++) {
                s[n] = fmaf(rq, s[n], du * sBC[l][n]);
                y = fmaf(s[n], sBC[l][NST+n], y);
                rq *= q;
            }
            y = fmaf(Dh, xv, y);
            const int m = mbase + l;
            float z = d_z[(size_t)m*Hsz + h];
            float sz = z / (1.f + __expf(-z));
            d_g16[(size_t)m*Hsz + h] = __float2half_rn(y * sz);
        }
    } else {
        for (int l = 0; l < CHUNK; l++) {
            const float dl = d_delta[(size_t)(mbase+l)*Hsz + h];
            const float xv = d_xc[(size_t)(mbase+l)*Hsz + h];
            const float du = dl * xv;
            float y = 0.f;
            #pragma unroll
            for (int n = 0; n < NST; n++) {
                float r = __expf(dl * a[n]);
                s[n] = fmaf(r, s[n], du * sBC[l][n]);
                y = fmaf(s[n], sBC[l][NST+n], y);
            }
            y = fmaf(Dh, xv, y);
            const int m = mbase + l;
            float z = d_z[(size_t)m*Hsz + h];
            float sz = z / (1.f + __expf(-z));
            d_g16[(size_t)m*Hsz + h] = __float2half_rn(y * sz);
        }
    }
}

// ---------------- launch ----------------
extern "C" void kernel_launch(void* const* d_in, const int* in_sizes, int n_in,
                              void* d_out, int out_size) {
    const float* x          = (const float*)d_in[0];
    const float* norm_w     = (const float*)d_in[1];
    const float* in_proj_w  = (const float*)d_in[2];
    const float* conv_w     = (const float*)d_in[3];
    const float* conv_b     = (const float*)d_in[4];
    const float* x_proj_w   = (const float*)d_in[5];
    const float* dt_proj_w  = (const float*)d_in[6];
    const float* dt_proj_b  = (const float*)d_in[7];
    const float* A_log      = (const float*)d_in[8];
    const float* Dv         = (const float*)d_in[9];
    const float* out_proj_w = (const float*)d_in[10];
    float* out = (float*)d_out;

    static int attr_done = 0;
    if (!attr_done) {
        cudaFuncSetAttribute(gemm_tc<0,false>, cudaFuncAttributeMaxDynamicSharedMemorySize, SMEM_TOT);
        cudaFuncSetAttribute(gemm_tc<1,true >, cudaFuncAttributeMaxDynamicSharedMemorySize, SMEM_TOT);
        cudaFuncSetAttribute(gemm_tc<2,false>, cudaFuncAttributeMaxDynamicSharedMemorySize, SMEM_TOT);
        attr_done = 1;
    }

    __half *p_h16, *p_xcp16, *p_g16, *p_ipw16, *p_opw16, *p_cwT16;
    float *p_z, *p_xc, *p_dbc, *p_dbcp, *p_delta;
    cudaGetSymbolAddress((void**)&p_h16, d_h16);
    cudaGetSymbolAddress((void**)&p_xcp16, d_xcp16);
    cudaGetSymbolAddress((void**)&p_g16, d_g16);
    cudaGetSymbolAddress((void**)&p_ipw16, d_ipw16);
    cudaGetSymbolAddress((void**)&p_opw16, d_opw16);
    cudaGetSymbolAddress((void**)&p_cwT16, d_cwT16);
    cudaGetSymbolAddress((void**)&p_z, d_z);
    cudaGetSymbolAddress((void**)&p_xc, d_xc);
    cudaGetSymbolAddress((void**)&p_dbc, d_dbc);
    cudaGetSymbolAddress((void**)&p_dbcp, d_dbcp);
    cudaGetSymbolAddress((void**)&p_delta, d_delta);

    // launch 1: fused prep (weights + conv transpose + aexp)
    prep_kernel<<<NB_IPW + NB_OPW + NB_AEXP + 16384, 256>>>(in_proj_w, out_proj_w, A_log, conv_w);
    // launch 2: rmsnorm
    rmsnorm_kernel<<<Msz, 256>>>(x, norm_w);
    // launch 3: in_proj  M=2048 N=4096 K=2048
    gemm_tc<0,false><<<dim3(2*Hsz/TN, Msz/TM), 512, SMEM_TOT>>>(
        p_h16, p_ipw16, nullptr, p_z, nullptr, Hsz, Hsz, Hsz);
    // launch 4 (ncu capture slot): conv  (K=8192 virtual over 4 taps)
    gemm_tc<1,true><<<dim3(Hsz/TN, Msz/TM), 512, SMEM_TOT>>>(
        p_xcp16, p_cwT16, p_xc, nullptr, conv_b, 4*Hsz, Hsz, Hsz);
    // dBC = xc @ x_proj_w.T  (exact fp32, split-K 16, 2 CTAs/SM)
    gemm_wt<4><<<dim3(1,16,DBC_SPLITS), 256>>>(p_xc, x_proj_w, p_dbcp,
                                               Msz, 96, Hsz, Hsz, Hsz, 96, nullptr);
    reduce_dbc<<<(Msz*96 + 255)/256, 256>>>();
    // delta = softplus(dBC[:, :64] @ dt_proj_w.T + b)  (exact fp32)
    gemm_wt<2><<<dim3(16,16,1), 256>>>(p_dbc, dt_proj_w, p_delta,
                                       Msz, Hsz, 64, 96, 64, Hsz, dt_proj_b);
    // chunked selective scan -> g (fp16)
    scan_pass1<<<Bsz*NCHUNK*(Hsz/128), 128>>>();
    scan_pass2<<<(Bsz*Hsz*NST + 255)/256, 256>>>();
    scan_pass3<<<Bsz*NCHUNK*(Hsz/128), 128>>>(Dv);
    // out = x + g @ out_proj_w.T
    gemm_tc<2,false><<<dim3(Hsz/TN, Msz/TM), 512, SMEM_TOT>>>(
        p_g16, p_opw16, out, nullptr, x, Hsz, Hsz, Hsz);
}

// round 15
// speedup vs baseline: 1.0838x; 1.0094x over previous
#include <cuda_runtime.h>
#include <cuda_fp16.h>
#include <math.h>
#include <stdint.h>

#define Bsz 2
#define Lsz 1024
#define Hsz 2048
#define Msz (Bsz*Lsz)          // 2048 rows
#define NST 16
#define CHUNK 128
#define NCHUNK (Lsz/CHUNK)     // 8
#define DBC_SPLITS 16

// tc gemm tile (fp16 path) — R11 proven config
#define TM 128
#define TN 256
#define KC 64
#define DST 4
#define RS 72                               // padded row stride in halves
#define OFFB_H (128*RS)                     // B offset in halves
#define STG_H ((128+256)*RS)                // halves per stage (27648)
#define SMEM_TOT (DST*STG_H*2)              // 221184 bytes

// ---------------- scratch ----------------
__device__ __half d_h16[(size_t)Msz*Hsz];       // rmsnorm out (fp16)
__device__ __half d_xcp16[(size_t)Msz*Hsz];     // in_proj xc half (fp16)
__device__ __half d_sz16[(size_t)Msz*Hsz];      // silu(z) (fp16)
__device__ float  d_xc[(size_t)Msz*Hsz];        // conv+silu out (fp32)
__device__ float  d_dbc[(size_t)Msz*96];
__device__ float  d_dbcp[(size_t)DBC_SPLITS*Msz*96];
__device__ float  d_delta[(size_t)Msz*Hsz];
__device__ __half d_g16[(size_t)Msz*Hsz];       // y*silu(z) (fp16)
__device__ float  d_Aexp[Hsz*NST];
__device__ float  d_P[(size_t)Bsz*NCHUNK*Hsz*NST];
__device__ float  d_S[(size_t)Bsz*NCHUNK*Hsz*NST];
__device__ float  d_I[(size_t)Bsz*NCHUNK*Hsz*NST];
__device__ __half d_ipw16[(size_t)2*Hsz*Hsz];   // in_proj_w fp16
__device__ __half d_opw16[(size_t)Hsz*Hsz];     // out_proj_w fp16
__device__ __half d_cwT16[(size_t)Hsz*4*Hsz];   // conv_w transposed [n][k=8192] fp16

// ---------------- helpers ----------------
__device__ __forceinline__ void mma16(float* c, const unsigned* a, const unsigned* b){
    asm volatile("mma.sync.aligned.m16n8k16.row.col.f32.f16.f16.f32 "
      "{%0,%1,%2,%3}, {%4,%5,%6,%7}, {%8,%9}, {%0,%1,%2,%3};"
      : "+f"(c[0]), "+f"(c[1]), "+f"(c[2]), "+f"(c[3])
      : "r"(a[0]), "r"(a[1]), "r"(a[2]), "r"(a[3]), "r"(b[0]), "r"(b[1]));
}
__device__ __forceinline__ void ldsm4(unsigned* r, uint32_t a){
    asm volatile("ldmatrix.sync.aligned.m8n8.x4.shared.b16 {%0,%1,%2,%3}, [%4];"
        : "=r"(r[0]), "=r"(r[1]), "=r"(r[2]), "=r"(r[3]) : "r"(a));
}
__device__ __forceinline__ uint32_t smem_u32(const void* p){
    uint32_t a; asm("{ .reg .u64 t; cvta.to.shared.u64 t, %1; cvt.u32.u64 %0, t; }" : "=r"(a) : "l"(p));
    return a;
}
__device__ __forceinline__ void cpa16(uint32_t dst, const __half* src, int srcsize){
    asm volatile("cp.async.cg.shared.global [%0], [%1], 16, %2;"
        :: "r"(dst), "l"(src), "r"(srcsize) : "memory");
}
__device__ __forceinline__ void cp_commit(){ asm volatile("cp.async.commit_group;" ::: "memory"); }
__device__ __forceinline__ void cp_wait2(){ asm volatile("cp.async.wait_group 2;" ::: "memory"); }

// ---------------- fused prep + rmsnorm kernel ----------------
#define NB_IPW 8192
#define NB_OPW 4096
#define NB_AEXP 128
#define NB_CWT 16384
#define NB_PREP (NB_IPW + NB_OPW + NB_AEXP + NB_CWT)
__global__ void prep_kernel(const float* __restrict__ ipw, const float* __restrict__ opw,
                            const float* __restrict__ alog, const float* __restrict__ cw,
                            const float* __restrict__ x, const float* __restrict__ w){
    __shared__ float tl[32][33];
    __shared__ float red[8];
    const int bid = blockIdx.x;
    const int t = threadIdx.x;
    if (bid < NB_IPW) {
        int i = bid*256 + t;
        float4 v = *(const float4*)(ipw + (size_t)i*4);
        __half2 h01 = __floats2half2_rn(v.x, v.y);
        __half2 h23 = __floats2half2_rn(v.z, v.w);
        *(uint2*)(d_ipw16 + (size_t)i*4) = make_uint2(*(unsigned*)&h01, *(unsigned*)&h23);
    } else if (bid < NB_IPW + NB_OPW) {
        int i = (bid - NB_IPW)*256 + t;
        float4 v = *(const float4*)(opw + (size_t)i*4);
        __half2 h01 = __floats2half2_rn(v.x, v.y);
        __half2 h23 = __floats2half2_rn(v.z, v.w);
        *(uint2*)(d_opw16 + (size_t)i*4) = make_uint2(*(unsigned*)&h01, *(unsigned*)&h23);
    } else if (bid < NB_IPW + NB_OPW + NB_AEXP) {
        int i = (bid - NB_IPW - NB_OPW)*256 + t;
        if (i < Hsz*NST) d_Aexp[i] = -expf(alog[i]);
    } else if (bid < NB_PREP) {
        const int id = bid - (NB_IPW + NB_OPW + NB_AEXP);
        const int k0 = (id & 255)*32, n0 = (id >> 8)*32;
        const int tx = t & 31, ty = t >> 5;
        #pragma unroll
        for (int d = 0; d < 4; d++)
            tl[ty + d*8][tx] = cw[(size_t)(k0+ty+d*8)*Hsz + n0 + tx];
        __syncthreads();
        #pragma unroll
        for (int d = 0; d < 4; d++)
            d_cwT16[(size_t)(n0+ty+d*8)*(4*Hsz) + k0 + tx] = __float2half_rn(tl[tx][ty+d*8]);
    } else {
        // rmsnorm rows
        const int m = bid - NB_PREP;
        const float* xr = x + (size_t)m*Hsz;
        float ss = 0.f;
        for (int i = t*4; i < Hsz; i += 1024) {
            float4 v = *(const float4*)(xr + i);
            ss += v.x*v.x + v.y*v.y + v.z*v.z + v.w*v.w;
        }
        #pragma unroll
        for (int o = 16; o; o >>= 1) ss += __shfl_xor_sync(0xffffffffu, ss, o);
        if ((t & 31) == 0) red[t >> 5] = ss;
        __syncthreads();
        if (t == 0) {
            float v = 0.f;
            #pragma unroll
            for (int j = 0; j < 8; j++) v += red[j];
            red[0] = rsqrtf(v * (1.0f/Hsz) + 1e-5f);
        }
        __syncthreads();
        const float sc = red[0];
        for (int i = t*4; i < Hsz; i += 1024) {
            float4 v = *(const float4*)(xr + i);
            float4 wv = *(const float4*)(w + i);
            __half2 h01 = __floats2half2_rn(v.x*sc*wv.x, v.y*sc*wv.y);
            __half2 h23 = __floats2half2_rn(v.z*sc*wv.z, v.w*sc*wv.w);
            *(uint2*)(d_h16 + (size_t)m*Hsz + i) = make_uint2(*(unsigned*)&h01, *(unsigned*)&h23);
        }
    }
}

// ====== fp16 tensor GEMM (R11 config): 512 thr, 128x256 tile, DST=4, rotation ======
// EPI 0: xc half -> fp16 xcp        EPI 3: z half -> silu -> fp16 sz
// EPI 1: conv bias+silu -> fp32 C   EPI 2: resid add -> fp32 C
template<int EPI, bool CONVA>
__global__ void __launch_bounds__(512, 1)
gemm_tc(const __half* __restrict__ A, const __half* __restrict__ W,
        float* __restrict__ C, const float* __restrict__ aux,
        int K, int lda, int ldc)
{
    extern __shared__ __align__(16) __half sm[];
    const uint32_t smb = smem_u32(sm);
    const int t = threadIdx.x;
    const int lane = t & 31, w = t >> 5;
    const int gid = lane >> 2, tig = lane & 3;
    const int wm = (w & 3) * 32, wn = (w >> 2) * 64;
    const int wrot = w & 3;
    const int n0 = blockIdx.x * TN, m0 = blockIdx.y * TM;
    const int nc = K / KC;

    uint32_t dstA[2], dstB[4];
    int rowA[2], kcA[2], rowB[4], kcB[4];
    #pragma unroll
    for (int i = 0; i < 2; i++) {
        int slot = t + 512*i;
        rowA[i] = slot >> 3; kcA[i] = (slot & 7) * 8;
        dstA[i] = smb + (uint32_t)(rowA[i]*RS + kcA[i])*2;
    }
    #pragma unroll
    for (int i = 0; i < 4; i++) {
        int slot = t + 512*i;
        rowB[i] = slot >> 3; kcB[i] = (slot & 7) * 8;
        dstB[i] = smb + (uint32_t)(OFFB_H + rowB[i]*RS + kcB[i])*2;
    }

    auto issue = [&](int c){
        if (c < nc) {
            const uint32_t so = (uint32_t)(c & (DST-1)) * (STG_H*2);
            const int kb = c * KC;
            if (!CONVA) {
                #pragma unroll
                for (int i = 0; i < 2; i++)
                    cpa16(dstA[i] + so, A + (size_t)(m0 + rowA[i])*lda + kb + kcA[i], 16);
            } else {
                const int tap = kb >> 11, kin = kb & (Hsz-1);
                #pragma unroll
                for (int i = 0; i < 2; i++) {
                    const int m = m0 + rowA[i];
                    int ls = (m & 1023) + tap - 3;
                    const int sz = (ls >= 0) ? 16 : 0;
                    if (ls < 0) ls = 0;
                    cpa16(dstA[i] + so, A + (size_t)((m & ~1023) + ls)*lda + kin + kcA[i], sz);
                }
            }
            #pragma unroll
            for (int i = 0; i < 4; i++)
                cpa16(dstB[i] + so, W + (size_t)(n0 + rowB[i])*K + kb + kcB[i], 16);
        }
        cp_commit();
    };

    uint32_t a_ad[2], b_ad[4];
    {
        const int arow = (lane & 15), acol = (lane >> 4) * 8;
        #pragma unroll
        for (int mi = 0; mi < 2; mi++)
            a_ad[mi] = smb + (uint32_t)(((wm + mi*16 + arow)*RS + acol))*2;
        const int brow = ((lane & 16) >> 1) + (lane & 7);
        const int bcol = (lane & 8);
        #pragma unroll
        for (int nq = 0; nq < 4; nq++)
            b_ad[nq] = smb + (uint32_t)((OFFB_H + (wn + nq*16 + brow)*RS + bcol))*2;
    }

    float acc[2][8][4];
    #pragma unroll
    for (int mi = 0; mi < 2; mi++)
        #pragma unroll
        for (int ni = 0; ni < 8; ni++)
            #pragma unroll
            for (int q = 0; q < 4; q++) acc[mi][ni][q] = 0.f;

    issue(0); issue(1); issue(2);
    for (int c = 0; c < nc; c++) {
        cp_wait2();
        __syncthreads();
        const uint32_t so = (uint32_t)(c & (DST-1)) * (STG_H*2);
        #pragma unroll
        for (int i = 0; i < 4; i++) {
            const int ks = (i + wrot) & 3;
            unsigned af[2][4], bf[4][4];
            ldsm4(af[0], a_ad[0] + so + ks*32);
            ldsm4(af[1], a_ad[1] + so + ks*32);
            #pragma unroll
            for (int nq = 0; nq < 4; nq++) ldsm4(bf[nq], b_ad[nq] + so + ks*32);
            #pragma unroll
            for (int mi = 0; mi < 2; mi++)
                #pragma unroll
                for (int ni = 0; ni < 8; ni++)
                    mma16(acc[mi][ni], af[mi], &bf[ni>>1][(ni&1)*2]);
        }
        issue(c + DST - 1);
    }

    #pragma unroll
    for (int mi = 0; mi < 2; mi++) {
        #pragma unroll
        for (int rr = 0; rr < 2; rr++) {
            const int m = m0 + wm + mi*16 + rr*8 + gid;
            #pragma unroll
            for (int ni = 0; ni < 8; ni++) {
                const int n = n0 + wn + ni*8 + tig*2;
                float v0 = acc[mi][ni][rr*2+0];
                float v1 = acc[mi][ni][rr*2+1];
                if (EPI == 0) {
                    __half2 hp = __floats2half2_rn(v0, v1);
                    *(unsigned*)&d_xcp16[(size_t)m*Hsz + n] = *(unsigned*)&hp;
                } else if (EPI == 3) {
                    float s0 = v0 / (1.f + __expf(-v0));
                    float s1 = v1 / (1.f + __expf(-v1));
                    __half2 hp = __floats2half2_rn(s0, s1);
                    *(unsigned*)&d_sz16[(size_t)m*Hsz + n] = *(unsigned*)&hp;
                } else if (EPI == 1) {
                    v0 += aux[n];   v1 += aux[n+1];
                    v0 = v0 / (1.f + __expf(-v0));
                    v1 = v1 / (1.f + __expf(-v1));
                    *(float2*)&C[(size_t)m*ldc + n] = make_float2(v0, v1);
                } else {
                    v0 += aux[(size_t)m*ldc + n];
                    v1 += aux[(size_t)m*ldc + n + 1];
                    *(float2*)&C[(size_t)m*ldc + n] = make_float2(v0, v1);
                }
            }
        }
    }
}

// ---------------- fp32 SIMT GEMM (exact; small ops), 2 CTAs/SM ----------------
template<int EPI>
__global__ void __launch_bounds__(256, 2)
gemm_wt(const float* __restrict__ A, const float* __restrict__ W,
        float* __restrict__ C, int M, int N, int K,
        int lda, int ldb, int ldc,
        const float* __restrict__ bias)
{
    __shared__ float As[8][128];
    __shared__ float Bs[8][128];
    const int t  = threadIdx.x;
    const int n0 = blockIdx.x * 128;
    const int m0 = blockIdx.y * 128;
    const int kslice = K / gridDim.z;
    const int kbeg = blockIdx.z * kslice;
    const int KT = kslice >> 3;

    const int ar = t >> 1;
    const int ak = (t & 1) * 4;
    const float* Ap = A + (size_t)(m0 + ar)*lda + kbeg + ak;
    const bool wok = (n0 + ar) < N;
    const float* Wp = W + (size_t)(n0 + ar)*ldb + kbeg + ak;

    float* Cb = C;
    if (EPI == 4) Cb = C + (size_t)blockIdx.z * M * ldc;

    const int tx = t & 15, ty = t >> 4;
    float acc[8][8];
    #pragma unroll
    for (int i = 0; i < 8; i++)
        #pragma unroll
        for (int j = 0; j < 8; j++) acc[i][j] = 0.f;

    float4 pa = *(const float4*)Ap;
    float4 pb = wok ? *(const float4*)Wp : make_float4(0.f,0.f,0.f,0.f);

    for (int kt = 0; kt < KT; ++kt) {
        As[ak+0][ar]=pa.x; As[ak+1][ar]=pa.y; As[ak+2][ar]=pa.z; As[ak+3][ar]=pa.w;
        Bs[ak+0][ar]=pb.x; Bs[ak+1][ar]=pb.y; Bs[ak+2][ar]=pb.z; Bs[ak+3][ar]=pb.w;
        __syncthreads();
        if (kt + 1 < KT) {
            pa = *(const float4*)(Ap + (size_t)(kt+1)*8);
            pb = wok ? *(const float4*)(Wp + (size_t)(kt+1)*8) : make_float4(0.f,0.f,0.f,0.f);
        }
        #pragma unroll
        for (int kk = 0; kk < 8; kk++) {
            float a[8], b[8];
            *(float4*)&a[0] = *(const float4*)&As[kk][ty*8];
            *(float4*)&a[4] = *(const float4*)&As[kk][ty*8+4];
            *(float4*)&b[0] = *(const float4*)&Bs[kk][tx*8];
            *(float4*)&b[4] = *(const float4*)&Bs[kk][tx*8+4];
            #pragma unroll
            for (int i = 0; i < 8; i++)
                #pragma unroll
                for (int j = 0; j < 8; j++)
                    acc[i][j] = fmaf(a[i], b[j], acc[i][j]);
        }
        __syncthreads();
    }

    #pragma unroll
    for (int i = 0; i < 8; i++) {
        const int m = m0 + ty*8 + i;
        #pragma unroll
        for (int j = 0; j < 8; j++) {
            const int n = n0 + tx*8 + j;
            if (n < N) {
                float v = acc[i][j];
                if (EPI == 2) { v += bias[n]; v = (v > 20.f) ? v : log1pf(__expf(v)); }
                Cb[(size_t)m*ldc + n] = v;
            }
        }
    }
}

__global__ void reduce_dbc() {
    int i = blockIdx.x*256 + threadIdx.x;
    if (i < Msz*96) {
        float s = 0.f;
        #pragma unroll
        for (int z = 0; z < DBC_SPLITS; z++) s += d_dbcp[(size_t)z*Msz*96 + i];
        d_dbc[i] = s;
    }
}

// ---------------- chunked selective scan (fast path: a[n] == -(n+1)) ----------------
__global__ void __launch_bounds__(128) scan_pass1() {
    __shared__ float sB[CHUNK][NST];
    const int bid = blockIdx.x;
    const int ht = bid & 15;
    const int c  = (bid >> 4) & 7;
    const int b  = bid >> 7;
    const int h  = ht*128 + threadIdx.x;
    const int mbase = b*Lsz + c*CHUNK;

    for (int j = threadIdx.x; j < CHUNK*NST; j += 128) {
        int l = j >> 4, n = j & 15;
        sB[l][n] = d_dbc[(size_t)(mbase+l)*96 + 64 + n];
    }
    __syncthreads();

    float a[NST], p[NST], s[NST];
    bool fastok = true;
    #pragma unroll
    for (int n = 0; n < NST; n++) {
        a[n] = d_Aexp[h*NST + n];
        p[n] = 1.f; s[n] = 0.f;
        fastok = fastok && (fabsf(a[n] + (float)(n+1)) <= 2e-6f*(float)(n+1));
    }

    if (fastok) {
        float Dsum = 0.f;
        for (int l = 0; l < CHUNK; l++) {
            const float dl = d_delta[(size_t)(mbase+l)*Hsz + h];
            const float xv = d_xc[(size_t)(mbase+l)*Hsz + h];
            const float q = __expf(-dl);
            const float du = dl * xv;
            Dsum += dl;
            float rq = q;
            #pragma unroll
            for (int n = 0; n < NST; n++) {
                s[n] = fmaf(rq, s[n], du * sB[l][n]);
                rq *= q;
            }
        }
        const float Q = __expf(-Dsum);
        float pq = Q;
        #pragma unroll
        for (int n = 0; n < NST; n++) { p[n] = pq; pq *= Q; }
    } else {
        for (int l = 0; l < CHUNK; l++) {
            const float dl = d_delta[(size_t)(mbase+l)*Hsz + h];
            const float xv = d_xc[(size_t)(mbase+l)*Hsz + h];
            const float du = dl * xv;
            #pragma unroll
            for (int n = 0; n < NST; n++) {
                float r = __expf(dl * a[n]);
                p[n] *= r;
                s[n] = fmaf(r, s[n], du * sB[l][n]);
            }
        }
    }
    size_t base = ((size_t)(b*NCHUNK + c)*Hsz + h)*NST;
    #pragma unroll
    for (int n = 0; n < NST; n++) { d_P[base+n] = p[n]; d_S[base+n] = s[n]; }
}

__global__ void scan_pass2() {
    int idx = blockIdx.x*256 + threadIdx.x;
    if (idx >= Bsz*Hsz*NST) return;
    int b  = idx / (Hsz*NST);
    int hn = idx % (Hsz*NST);
    float st = 0.f;
    for (int c = 0; c < NCHUNK; c++) {
        size_t o = (size_t)(b*NCHUNK + c)*Hsz*NST + hn;
        d_I[o] = st;
        st = d_P[o]*st + d_S[o];
    }
}

__global__ void __launch_bounds__(128) scan_pass3(const float* __restrict__ Din) {
    __shared__ float sBC[CHUNK][2*NST];
    const int bid = blockIdx.x;
    const int ht = bid & 15;
    const int c  = (bid >> 4) & 7;
    const int b  = bid >> 7;
    const int h  = ht*128 + threadIdx.x;
    const int mbase = b*Lsz + c*CHUNK;

    for (int j = threadIdx.x; j < CHUNK*2*NST; j += 128) {
        int l = j >> 5, cc = j & 31;
        sBC[l][cc] = d_dbc[(size_t)(mbase+l)*96 + 64 + cc];
    }
    __syncthreads();

    float a[NST], s[NST];
    size_t base = ((size_t)(b*NCHUNK + c)*Hsz + h)*NST;
    bool fastok = true;
    #pragma unroll
    for (int n = 0; n < NST; n++) {
        a[n] = d_Aexp[h*NST + n];
        s[n] = d_I[base+n];
        fastok = fastok && (fabsf(a[n] + (float)(n+1)) <= 2e-6f*(float)(n+1));
    }
    const float Dh = Din[h];

    if (fastok) {
        for (int l = 0; l < CHUNK; l++) {
            const float dl = d_delta[(size_t)(mbase+l)*Hsz + h];
            const float xv = d_xc[(size_t)(mbase+l)*Hsz + h];
            const float q = __expf(-dl);
            const float du = dl * xv;
            float y = 0.f, rq = q;
            #pragma unroll
            for (int n = 0; n < NST; n++) {
                s[n] = fmaf(rq, s[n], du * sBC[l][n]);
                y = fmaf(s[n], sBC[l][NST+n], y);
                rq *= q;
            }
            y = fmaf(Dh, xv, y);
            const int m = mbase + l;
            float sz = __half2float(d_sz16[(size_t)m*Hsz + h]);
            d_g16[(size_t)m*Hsz + h] = __float2half_rn(y * sz);
        }
    } else {
        for (int l = 0; l < CHUNK; l++) {
            const float dl = d_delta[(size_t)(mbase+l)*Hsz + h];
            const float xv = d_xc[(size_t)(mbase+l)*Hsz + h];
            const float du = dl * xv;
            float y = 0.f;
            #pragma unroll
            for (int n = 0; n < NST; n++) {
                float r = __expf(dl * a[n]);
                s[n] = fmaf(r, s[n], du * sBC[l][n]);
                y = fmaf(s[n], sBC[l][NST+n], y);
            }
            y = fmaf(Dh, xv, y);
            const int m = mbase + l;
            float sz = __half2float(d_sz16[(size_t)m*Hsz + h]);
            d_g16[(size_t)m*Hsz + h] = __float2half_rn(y * sz);
        }
    }
}

// ---------------- launch ----------------
extern "C" void kernel_launch(void* const* d_in, const int* in_sizes, int n_in,
                              void* d_out, int out_size) {
    const float* x          = (const float*)d_in[0];
    const float* norm_w     = (const float*)d_in[1];
    const float* in_proj_w  = (const float*)d_in[2];
    const float* conv_w     = (const float*)d_in[3];
    const float* conv_b     = (const float*)d_in[4];
    const float* x_proj_w   = (const float*)d_in[5];
    const float* dt_proj_w  = (const float*)d_in[6];
    const float* dt_proj_b  = (const float*)d_in[7];
    const float* A_log      = (const float*)d_in[8];
    const float* Dv         = (const float*)d_in[9];
    const float* out_proj_w = (const float*)d_in[10];
    float* out = (float*)d_out;

    static int attr_done = 0;
    if (!attr_done) {
        cudaFuncSetAttribute(gemm_tc<0,false>, cudaFuncAttributeMaxDynamicSharedMemorySize, SMEM_TOT);
        cudaFuncSetAttribute(gemm_tc<3,false>, cudaFuncAttributeMaxDynamicSharedMemorySize, SMEM_TOT);
        cudaFuncSetAttribute(gemm_tc<1,true >, cudaFuncAttributeMaxDynamicSharedMemorySize, SMEM_TOT);
        cudaFuncSetAttribute(gemm_tc<2,false>, cudaFuncAttributeMaxDynamicSharedMemorySize, SMEM_TOT);
        attr_done = 1;
    }

    __half *p_h16, *p_xcp16, *p_g16, *p_ipw16, *p_opw16, *p_cwT16;
    float *p_xc, *p_dbc, *p_dbcp, *p_delta;
    cudaGetSymbolAddress((void**)&p_h16, d_h16);
    cudaGetSymbolAddress((void**)&p_xcp16, d_xcp16);
    cudaGetSymbolAddress((void**)&p_g16, d_g16);
    cudaGetSymbolAddress((void**)&p_ipw16, d_ipw16);
    cudaGetSymbolAddress((void**)&p_opw16, d_opw16);
    cudaGetSymbolAddress((void**)&p_cwT16, d_cwT16);
    cudaGetSymbolAddress((void**)&p_xc, d_xc);
    cudaGetSymbolAddress((void**)&p_dbc, d_dbc);
    cudaGetSymbolAddress((void**)&p_dbcp, d_dbcp);
    cudaGetSymbolAddress((void**)&p_delta, d_delta);

    // launch 1: fused prep (weights + conv transpose + aexp + rmsnorm)
    prep_kernel<<<NB_PREP + Msz, 256>>>(in_proj_w, out_proj_w, A_log, conv_w, x, norm_w);
    // launch 2: in_proj xc-half (single wave, 128 CTAs): xcp16 = h @ W[0:H]^T
    gemm_tc<0,false><<<dim3(Hsz/TN, Msz/TM), 512, SMEM_TOT>>>(
        p_h16, p_ipw16, nullptr, nullptr, Hsz, Hsz, Hsz);
    // launch 3: in_proj z-half (single wave): sz16 = silu(h @ W[H:2H]^T)
    gemm_tc<3,false><<<dim3(Hsz/TN, Msz/TM), 512, SMEM_TOT>>>(
        p_h16, p_ipw16 + (size_t)Hsz*Hsz, nullptr, nullptr, Hsz, Hsz, Hsz);
    // launch 4: conv  (K=8192 virtual over 4 taps)
    gemm_tc<1,true><<<dim3(Hsz/TN, Msz/TM), 512, SMEM_TOT>>>(
        p_xcp16, p_cwT16, p_xc, conv_b, 4*Hsz, Hsz, Hsz);
    // dBC = xc @ x_proj_w.T  (exact fp32, split-K 16, 2 CTAs/SM)
    gemm_wt<4><<<dim3(1,16,DBC_SPLITS), 256>>>(p_xc, x_proj_w, p_dbcp,
                                               Msz, 96, Hsz, Hsz, Hsz, 96, nullptr);
    reduce_dbc<<<(Msz*96 + 255)/256, 256>>>();
    // delta = softplus(dBC[:, :64] @ dt_proj_w.T + b)  (exact fp32)
    gemm_wt<2><<<dim3(16,16,1), 256>>>(p_dbc, dt_proj_w, p_delta,
                                       Msz, Hsz, 64, 96, 64, Hsz, dt_proj_b);
    // chunked selective scan -> g (fp16)
    scan_pass1<<<Bsz*NCHUNK*(Hsz/128), 128>>>();
    scan_pass2<<<(Bsz*Hsz*NST + 255)/256, 256>>>();
    scan_pass3<<<Bsz*NCHUNK*(Hsz/128), 128>>>(Dv);
    // out = x + g @ out_proj_w.T
    gemm_tc<2,false><<<dim3(Hsz/TN, Msz/TM), 512, SMEM_TOT>>>(
        p_g16, p_opw16, out, x, Hsz, Hsz, Hsz);
}